// round 17
// baseline (speedup 1.0000x reference)
#include <cuda_runtime.h>
#include <cuda_fp16.h>
#include <cuda_pipeline.h>
#include <mma.h>
#include <math.h>

using namespace nvcuda;

#define NN   100000
#define EE   500000
#define ETOT (EE + NN)
#define GG   1000
#define WOFF 65536   // per-layer offset in fp16 weight pool

// ---------------- device scratch (static; no runtime allocation) ----------------
__device__ __half d_bufA[(size_t)NN * 256];    // fp16 node features
__device__ __half d_bufBh[(size_t)NN * 256];   // fp16 scratch (gemm out / agg-pre out)
__device__ __half d_wh[5 * WOFF];              // fp16 weights per layer
__device__ float d_as0[NN], d_ad0[NN];         // alpha ping
__device__ float d_as1[NN], d_ad1[NN];         // alpha pong
__device__ float d_was_all[5 * 256];           // W_l^T a_s per layer
__device__ float d_wad_all[5 * 256];           // W_l^T a_d per layer
__device__ int   d_rowptr[NN + 1];
__device__ int   d_cur[NN];
__device__ int   d_col[ETOT];
__device__ float d_gsum[GG * 32];
__device__ float d_gcnt[GG];
__device__ int   d_blocksum[160];

// ---------------- prep (ALL layers, parallel): w_as = W^T a_s, w_ad = W^T a_d ----
struct PrepArgs {
    const float* W[5];
    const float* as_[5];
    const float* ad_[5];
    int I[5];
    int O[5];
};
__global__ void prep_all_kernel(PrepArgs p) {
    __shared__ float sha[4], shd[4];
    int l = blockIdx.y;
    int k = blockIdx.x;
    int I = p.I[l];
    if (k >= I) return;
    int O = p.O[l];
    const float* W = p.W[l];
    const float* as_ = p.as_[l];
    const float* ad_ = p.ad_[l];
    float sa = 0.f, sd = 0.f;
    for (int o = threadIdx.x; o < O; o += 128) {
        float w = W[(size_t)o * I + k];
        sa += w * as_[o];
        sd += w * ad_[o];
    }
    int lane = threadIdx.x & 31, wid = threadIdx.x >> 5;
#pragma unroll
    for (int o = 16; o; o >>= 1) {
        sa += __shfl_xor_sync(0xffffffffu, sa, o);
        sd += __shfl_xor_sync(0xffffffffu, sd, o);
    }
    if (lane == 0) { sha[wid] = sa; shd[wid] = sd; }
    __syncthreads();
    if (threadIdx.x == 0) {
        d_was_all[l * 256 + k] = sha[0] + sha[1] + sha[2] + sha[3];
        d_wad_all[l * 256 + k] = shd[0] + shd[1] + shd[2] + shd[3];
    }
}

// ---------------- convert all layer weights to fp16 ------------------------------
__global__ void wconv_kernel(PrepArgs p) {
    int l = blockIdx.y;
    int total = p.I[l] * p.O[l];
    const float* W = p.W[l];
    __half* Wh = d_wh + l * WOFF;
    for (int i = blockIdx.x * 256 + threadIdx.x; i < total; i += gridDim.x * 256)
        Wh[i] = __float2half(W[i]);
}

// ---------------- MLP: x[N,1]->16->32->64 relu; fused layer-1 alpha + deg init ---
__global__ void mlp_kernel(const float* __restrict__ x,
                           const float* __restrict__ w1, const float* __restrict__ b1,
                           const float* __restrict__ w2, const float* __restrict__ b2,
                           const float* __restrict__ w3, const float* __restrict__ b3,
                           __half* __restrict__ out,
                           const float* __restrict__ was, const float* __restrict__ wad,
                           float* __restrict__ as_out, float* __restrict__ ad_out, int n) {
    __shared__ float s_w1[16], s_b1[16];
    __shared__ float s_w2t[16 * 32];
    __shared__ float s_b2[32];
    __shared__ float s_w3t[32 * 64];
    __shared__ float s_b3[64];
    __shared__ float s_was[64], s_wad[64];

    int tid = threadIdx.x;
    int gt = blockIdx.x * blockDim.x + tid;
    if (gt < n) d_cur[gt] = 1;   // CSR degree init (self loop), folded in
    if (tid < 16) { s_w1[tid] = w1[tid]; s_b1[tid] = b1[tid]; }
    if (tid < 32) s_b2[tid] = b2[tid];
    if (tid < 64) { s_b3[tid] = b3[tid]; s_was[tid] = was[tid]; s_wad[tid] = wad[tid]; }
    for (int idx = tid; idx < 32 * 16; idx += blockDim.x) {
        int o = idx / 16, k = idx % 16;
        s_w2t[k * 32 + o] = w2[idx];
    }
    for (int idx = tid; idx < 64 * 32; idx += blockDim.x) {
        int o = idx / 32, k = idx % 32;
        s_w3t[k * 64 + o] = w3[idx];
    }
    __syncthreads();

    int warp = gt >> 5;
    int lane = tid & 31;
    if (warp >= n) return;

    float xv = x[warp];
    float h1[16];
#pragma unroll
    for (int j = 0; j < 16; j++) {
        float v = s_w1[j] * xv + s_b1[j];
        h1[j] = v > 0.f ? v : 0.f;
    }
    float h2;
    {
        float acc = s_b2[lane];
#pragma unroll
        for (int k = 0; k < 16; k++) acc += s_w2t[k * 32 + lane] * h1[k];
        h2 = acc > 0.f ? acc : 0.f;
    }
    float v0, v1;
#pragma unroll
    for (int j2 = 0; j2 < 2; j2++) {
        int j = lane + 32 * j2;
        float acc = s_b3[j];
#pragma unroll
        for (int k = 0; k < 32; k++)
            acc += __shfl_sync(0xffffffffu, h2, k) * s_w3t[k * 64 + j];
        acc = acc > 0.f ? acc : 0.f;
        out[(size_t)warp * 64 + j] = __float2half(acc);
        if (j2 == 0) v0 = acc; else v1 = acc;
    }
    float sa = v0 * s_was[lane] + v1 * s_was[lane + 32];
    float sd = v0 * s_wad[lane] + v1 * s_wad[lane + 32];
#pragma unroll
    for (int o = 16; o; o >>= 1) {
        sa += __shfl_xor_sync(0xffffffffu, sa, o);
        sd += __shfl_xor_sync(0xffffffffu, sd, o);
    }
    if (lane == 0) { as_out[warp] = sa; ad_out[warp] = sd; }
}

// ---------------- CSR build ------------------------------------------------------
__global__ void count_deg_kernel(const int* __restrict__ dst, int E) {
    int e = blockIdx.x * blockDim.x + threadIdx.x;
    if (e < E) atomicAdd(&d_cur[dst[e]], 1);
}
__global__ void scan_block_kernel(int n) {
    __shared__ int warpsum[32];
    int i = blockIdx.x * 1024 + threadIdx.x;
    int lane = threadIdx.x & 31, wid = threadIdx.x >> 5;
    int v = (i < n) ? d_cur[i] : 0;
    int x = v;
#pragma unroll
    for (int o = 1; o < 32; o <<= 1) {
        int t = __shfl_up_sync(0xffffffffu, x, o);
        if (lane >= o) x += t;
    }
    if (lane == 31) warpsum[wid] = x;
    __syncthreads();
    if (wid == 0) {
        int s = warpsum[lane];
#pragma unroll
        for (int o = 1; o < 32; o <<= 1) {
            int t = __shfl_up_sync(0xffffffffu, s, o);
            if (lane >= o) s += t;
        }
        warpsum[lane] = s;
    }
    __syncthreads();
    int base = wid ? warpsum[wid - 1] : 0;
    int incl = base + x;
    if (i < n) d_rowptr[i] = incl - v;
    if (threadIdx.x == 1023) d_blocksum[blockIdx.x] = incl;
}
__global__ void scan_add_fill_kernel(int n, int nb) {
    __shared__ int offs;
    if (threadIdx.x < 32) {
        int sum = 0;
        for (int j = (int)threadIdx.x; j < (int)blockIdx.x; j += 32)
            sum += d_blocksum[j];
#pragma unroll
        for (int o = 16; o; o >>= 1) sum += __shfl_xor_sync(0xffffffffu, sum, o);
        if (threadIdx.x == 0) offs = sum;
    }
    __syncthreads();
    int i = blockIdx.x * 1024 + threadIdx.x;
    if (i < n) {
        int r = d_rowptr[i] + offs;
        d_rowptr[i] = r;
        d_col[r] = i;
        d_cur[i] = r + 1;
    } else if (i == n) {
        int tot = 0;
        for (int j = 0; j < nb; j++) tot += d_blocksum[j];
        d_rowptr[n] = tot;
    }
}
__global__ void scatter_edges_kernel(const int* __restrict__ src,
                                     const int* __restrict__ dst, int E) {
    int e = blockIdx.x * blockDim.x + threadIdx.x;
    if (e < E) {
        int p = atomicAdd(&d_cur[dst[e]], 1);
        d_col[p] = src[e];
    }
}

// ---------------- fp16 HMMA GEMM, 3-stage cp.async, optional fused epilogue ------
#define HLD 40
#define GBN 64
template <int FUSE>
__global__ void __launch_bounds__(512, 2)
gemm_h_kernel(const __half* __restrict__ A, const __half* __restrict__ Wh,
              __half* __restrict__ C,
              const float* __restrict__ bias,
              const float* __restrict__ wasn, const float* __restrict__ wadn,
              float* __restrict__ as_out, float* __restrict__ ad_out,
              int n, int I, int O) {
    constexpr int ASTG = 128 * HLD;
    constexpr int BSTG = GBN * HLD;
    constexpr int STG  = ASTG + BSTG;
    constexpr int SST = GBN + 8;
    constexpr int POOLB = 3 * STG * 2;                    // 3-stage pipeline bytes
    constexpr int STAGB = 64 * SST * 4;
    constexpr int POOLF = ((POOLB > STAGB ? POOLB : STAGB) + 3) / 4;
    __shared__ float smf[POOLF];
    __shared__ float s_bias[GBN], s_wasb[GBN], s_wadb[GBN];
    __half* smh = (__half*)smf;

    int tid = threadIdx.x;
    int w = tid >> 5;
    int wm = w & 3, wn = w >> 2;
    int bm = blockIdx.y * 128, bn = blockIdx.x * GBN;

    if (FUSE && tid < GBN) {
        int c = bn + tid;
        s_bias[tid] = (c < O) ? bias[c] : 0.f;
        s_wasb[tid] = (c < O) ? wasn[c] : 0.f;
        s_wadb[tid] = (c < O) ? wadn[c] : 0.f;
    }

    float* Ss = smf;

    wmma::fragment<wmma::accumulator, 16, 16, 16, float> acc[2];
    wmma::fill_fragment(acc[0], 0.f);
    wmma::fill_fragment(acc[1], 0.f);

    auto load_tiles = [&](int slot, int kb) {
        __half* Ad = smh + slot * STG;
        __half* Bd = Ad + ASTG;
        {
            int r = tid >> 2, kq = (tid & 3) * 8;
            int ar = bm + r;
            const __half* src = A + (size_t)(ar < n ? ar : 0) * I + kb + kq;
            __pipeline_memcpy_async(Ad + r * HLD + kq, src, 16, (ar < n) ? 0 : 16);
        }
        if (tid < 256) {
            int r = tid >> 2, kq = (tid & 3) * 8;
            int br = bn + r;
            const __half* src = Wh + (size_t)(br < O ? br : 0) * I + kb + kq;
            __pipeline_memcpy_async(Bd + r * HLD + kq, src, 16, (br < O) ? 0 : 16);
        }
    };

    int nk = I >> 5;        // >= 2 for all layers
    load_tiles(0, 0);
    __pipeline_commit();
    load_tiles(1, 32);
    __pipeline_commit();

    int buf = 0;
    for (int it = 0; it < nk; it++) {
        if (it + 1 < nk) __pipeline_wait_prior(1);
        else             __pipeline_wait_prior(0);
        __syncthreads();
        if (it + 2 < nk) {
            int slot = buf + 2; if (slot >= 3) slot -= 3;
            load_tiles(slot, (it + 2) << 5);
            __pipeline_commit();
        }
        __half* Ac = smh + buf * STG;
        __half* Bc = Ac + ASTG;
#pragma unroll
        for (int kk = 0; kk < 32; kk += 16) {
            wmma::fragment<wmma::matrix_a, 16, 16, 16, __half, wmma::row_major> af[2];
            wmma::fragment<wmma::matrix_b, 16, 16, 16, __half, wmma::col_major> bf;
            wmma::load_matrix_sync(af[0], Ac + (wm * 32) * HLD + kk, HLD);
            wmma::load_matrix_sync(af[1], Ac + (wm * 32 + 16) * HLD + kk, HLD);
            wmma::load_matrix_sync(bf, Bc + (wn * 16) * HLD + kk, HLD);
            wmma::mma_sync(acc[0], af[0], bf, acc[0]);
            wmma::mma_sync(acc[1], af[1], bf, acc[1]);
        }
        buf++; if (buf == 3) buf = 0;
    }
    __syncthreads();

#pragma unroll
    for (int h = 0; h < 2; h++) {
        if ((wm >> 1) == h) {
            int rb_ = (wm & 1) * 32;
            wmma::store_matrix_sync(Ss + rb_ * SST + wn * 16, acc[0], SST,
                                    wmma::mem_row_major);
            wmma::store_matrix_sync(Ss + (rb_ + 16) * SST + wn * 16, acc[1], SST,
                                    wmma::mem_row_major);
        }
        __syncthreads();
        {
            int r = tid >> 3;
            int c0 = (tid & 7) * 8;
            int gr = bm + h * 64 + r;
            bool valid = (gr < n) && (bn + c0 < O);
            if (FUSE) {
                float sa = 0.f, sd = 0.f;
                if (valid) {
                    const float* srow = Ss + r * SST + c0;
                    __half hh[8];
#pragma unroll
                    for (int j = 0; j < 8; j++) {
                        float t = srow[j] + s_bias[c0 + j];
                        t = t > 0.f ? t : 0.f;
                        hh[j] = __float2half(t);
                        sa += t * s_wasb[c0 + j];
                        sd += t * s_wadb[c0 + j];
                    }
                    __half2 p0 = __halves2half2(hh[0], hh[1]);
                    __half2 p1 = __halves2half2(hh[2], hh[3]);
                    __half2 p2 = __halves2half2(hh[4], hh[5]);
                    __half2 p3 = __halves2half2(hh[6], hh[7]);
                    uint4 u;
                    u.x = *(unsigned*)&p0; u.y = *(unsigned*)&p1;
                    u.z = *(unsigned*)&p2; u.w = *(unsigned*)&p3;
                    *(uint4*)(C + (size_t)gr * O + bn + c0) = u;
                }
#pragma unroll
                for (int m = 4; m; m >>= 1) {
                    sa += __shfl_xor_sync(0xffffffffu, sa, m);
                    sd += __shfl_xor_sync(0xffffffffu, sd, m);
                }
                if (valid && (tid & 7) == 0) {
                    atomicAdd(&as_out[gr], sa);
                    atomicAdd(&ad_out[gr], sd);
                }
            } else if (valid) {
                const float* srow = Ss + r * SST + c0;
                __half2 h0 = __floats2half2_rn(srow[0], srow[1]);
                __half2 h1 = __floats2half2_rn(srow[2], srow[3]);
                __half2 h2 = __floats2half2_rn(srow[4], srow[5]);
                __half2 h3 = __floats2half2_rn(srow[6], srow[7]);
                uint4 u;
                u.x = *(unsigned*)&h0; u.y = *(unsigned*)&h1;
                u.z = *(unsigned*)&h2; u.w = *(unsigned*)&h3;
                *(uint4*)(C + (size_t)gr * O + bn + c0) = u;
            }
        }
        __syncthreads();
    }
}

// ---------------- agg-PRE (input space) -------------------------------------------
template <int CPL>   // I/32: 2 or 4
__global__ void gat_agg_pre_kernel(const __half* __restrict__ xin,
                                   __half* __restrict__ yout,
                                   const float* __restrict__ as_in,
                                   const float* __restrict__ ad_in,
                                   float* __restrict__ as_zero,
                                   float* __restrict__ ad_zero,
                                   int n, int I) {
    int tid = threadIdx.x;
    int gt = blockIdx.x * blockDim.x + tid;
    if (gt < n) { as_zero[gt] = 0.f; ad_zero[gt] = 0.f; }
    int warp = gt >> 5;
    int lane = tid & 31;
    if (warp >= n) return;
    int s = d_rowptr[warp];
    int e = d_rowptr[warp + 1];
    float adi = ad_in[warp];

    float den = 0.f;
    float acc[CPL];
#pragma unroll
    for (int c = 0; c < CPL; c++) acc[c] = 0.f;

    for (int p0 = s; p0 < e; p0 += 32) {
        int p = p0 + lane;
        float wgt = 0.f;
        int src = 0;
        if (p < e) {
            src = d_col[p];
            float v = as_in[src] + adi;
            v = v > 0.f ? v : 0.2f * v;
            wgt = __expf(fminf(v, 70.f));
            den += wgt;
        }
        int cnt = min(32, e - p0);
        int q = 0;
        for (; q + 1 < cnt; q += 2) {
            float wq0 = __shfl_sync(0xffffffffu, wgt, q);
            int   sq0 = __shfl_sync(0xffffffffu, src, q);
            float wq1 = __shfl_sync(0xffffffffu, wgt, q + 1);
            int   sq1 = __shfl_sync(0xffffffffu, src, q + 1);
            const __half* r0 = xin + (size_t)sq0 * I;
            const __half* r1 = xin + (size_t)sq1 * I;
            if (CPL == 2) {
                float2 a0 = __half22float2(((const __half2*)r0)[lane]);
                float2 a1 = __half22float2(((const __half2*)r1)[lane]);
                acc[0] += wq0 * a0.x + wq1 * a1.x;
                acc[1] += wq0 * a0.y + wq1 * a1.y;
            } else {
                uint2 u0 = ((const uint2*)r0)[lane];
                uint2 u1 = ((const uint2*)r1)[lane];
                float2 a0 = __half22float2(*(const __half2*)&u0.x);
                float2 b0 = __half22float2(*(const __half2*)&u0.y);
                float2 a1 = __half22float2(*(const __half2*)&u1.x);
                float2 b1 = __half22float2(*(const __half2*)&u1.y);
                acc[0] += wq0 * a0.x + wq1 * a1.x;
                acc[1] += wq0 * a0.y + wq1 * a1.y;
                acc[2] += wq0 * b0.x + wq1 * b1.x;
                acc[3] += wq0 * b0.y + wq1 * b1.y;
            }
        }
        if (q < cnt) {
            float wq = __shfl_sync(0xffffffffu, wgt, q);
            int   sq = __shfl_sync(0xffffffffu, src, q);
            const __half* row = xin + (size_t)sq * I;
            if (CPL == 2) {
                float2 f = __half22float2(((const __half2*)row)[lane]);
                acc[0] += wq * f.x; acc[1] += wq * f.y;
            } else {
                uint2 u0 = ((const uint2*)row)[lane];
                float2 f0 = __half22float2(*(const __half2*)&u0.x);
                float2 f1 = __half22float2(*(const __half2*)&u0.y);
                acc[0] += wq * f0.x; acc[1] += wq * f0.y;
                acc[2] += wq * f1.x; acc[3] += wq * f1.y;
            }
        }
    }
#pragma unroll
    for (int o = 16; o; o >>= 1) den += __shfl_xor_sync(0xffffffffu, den, o);
    float inv = 1.f / den;

    __half* orow = yout + (size_t)warp * I;
    if (CPL == 2) {
        ((__half2*)orow)[lane] = __floats2half2_rn(acc[0] * inv, acc[1] * inv);
    } else {
        __half2 h0 = __floats2half2_rn(acc[0] * inv, acc[1] * inv);
        __half2 h1 = __floats2half2_rn(acc[2] * inv, acc[3] * inv);
        uint2 u; u.x = *(unsigned*)&h0; u.y = *(unsigned*)&h1;
        ((uint2*)orow)[lane] = u;
    }
}

// ---------------- agg-POST (output space): R13-proven -----------------------------
template <int CPL, bool ZPOOL, bool POOL, bool ALPHA>
__global__ void gat_agg_kernel(const __half* __restrict__ hlin,
                               const float* __restrict__ bias,
                               __half* __restrict__ out,
                               const float* __restrict__ as_in,
                               const float* __restrict__ ad_in,
                               float* __restrict__ as_out,
                               float* __restrict__ ad_out,
                               const float* __restrict__ was_next,
                               const float* __restrict__ wad_next,
                               const int* __restrict__ batch, int n, int O) {
    __shared__ float s_was[256], s_wad[256];
    int tid = threadIdx.x;
    if (ALPHA && tid < O) { s_was[tid] = was_next[tid]; s_wad[tid] = wad_next[tid]; }
    if (ALPHA) __syncthreads();

    int gt = blockIdx.x * blockDim.x + tid;
    if (ZPOOL) {
        if (gt < GG * 32) d_gsum[gt] = 0.f;
        if (gt < GG) d_gcnt[gt] = 0.f;
    }
    int warp = gt >> 5;
    int lane = tid & 31;
    if (warp >= n) return;
    int s = d_rowptr[warp];
    int e = d_rowptr[warp + 1];
    float adi = ad_in[warp];

    float den = 0.f;
    float acc[CPL];
#pragma unroll
    for (int c = 0; c < CPL; c++) acc[c] = 0.f;

    for (int p0 = s; p0 < e; p0 += 32) {
        int p = p0 + lane;
        float wgt = 0.f;
        int src = 0;
        if (p < e) {
            src = d_col[p];
            float v = as_in[src] + adi;
            v = v > 0.f ? v : 0.2f * v;
            wgt = __expf(fminf(v, 70.f));
            den += wgt;
        }
        int cnt = min(32, e - p0);
        int q = 0;
        for (; q + 1 < cnt; q += 2) {
            float wq0 = __shfl_sync(0xffffffffu, wgt, q);
            int   sq0 = __shfl_sync(0xffffffffu, src, q);
            float wq1 = __shfl_sync(0xffffffffu, wgt, q + 1);
            int   sq1 = __shfl_sync(0xffffffffu, src, q + 1);
            const __half* r0 = hlin + (size_t)sq0 * O;
            const __half* r1 = hlin + (size_t)sq1 * O;
            if (CPL == 1) {
                acc[0] += wq0 * __half2float(r0[lane]) + wq1 * __half2float(r1[lane]);
            } else if (CPL == 2) {
                float2 a0 = __half22float2(((const __half2*)r0)[lane]);
                float2 a1 = __half22float2(((const __half2*)r1)[lane]);
                acc[0] += wq0 * a0.x + wq1 * a1.x;
                acc[1] += wq0 * a0.y + wq1 * a1.y;
            } else {   // CPL == 4
                uint2 u0 = ((const uint2*)r0)[lane];
                uint2 u1 = ((const uint2*)r1)[lane];
                float2 a0 = __half22float2(*(const __half2*)&u0.x);
                float2 b0 = __half22float2(*(const __half2*)&u0.y);
                float2 a1 = __half22float2(*(const __half2*)&u1.x);
                float2 b1 = __half22float2(*(const __half2*)&u1.y);
                acc[0] += wq0 * a0.x + wq1 * a1.x;
                acc[1] += wq0 * a0.y + wq1 * a1.y;
                acc[2] += wq0 * b0.x + wq1 * b1.x;
                acc[3] += wq0 * b0.y + wq1 * b1.y;
            }
        }
        if (q < cnt) {
            float wq = __shfl_sync(0xffffffffu, wgt, q);
            int   sq = __shfl_sync(0xffffffffu, src, q);
            const __half* row = hlin + (size_t)sq * O;
            if (CPL == 1) {
                acc[0] += wq * __half2float(row[lane]);
            } else if (CPL == 2) {
                float2 f = __half22float2(((const __half2*)row)[lane]);
                acc[0] += wq * f.x; acc[1] += wq * f.y;
            } else {
                uint2 u0 = ((const uint2*)row)[lane];
                float2 f0 = __half22float2(*(const __half2*)&u0.x);
                float2 f1 = __half22float2(*(const __half2*)&u0.y);
                acc[0] += wq * f0.x; acc[1] += wq * f0.y;
                acc[2] += wq * f1.x; acc[3] += wq * f1.y;
            }
        }
    }
#pragma unroll
    for (int o = 16; o; o >>= 1) den += __shfl_xor_sync(0xffffffffu, den, o);
    float inv = 1.f / den;

    float v[CPL];
#pragma unroll
    for (int c = 0; c < CPL; c++) {
        float t = acc[c] * inv + bias[CPL * lane + c];
        v[c] = t > 0.f ? t : 0.f;
    }

    __half* orow = out + (size_t)warp * O;
    if (CPL == 1) {
        orow[lane] = __float2half(v[0]);
        if (POOL) {
            int b = batch[warp];
            atomicAdd(&d_gsum[b * 32 + lane], v[0]);
            if (lane == 0) atomicAdd(&d_gcnt[b], 1.f);
        }
    } else if (CPL == 2) {
        ((__half2*)orow)[lane] = __floats2half2_rn(v[0], v[1]);
    } else {
        __half2 h0 = __floats2half2_rn(v[0], v[1]);
        __half2 h1 = __floats2half2_rn(v[2], v[3]);
        uint2 u; u.x = *(unsigned*)&h0; u.y = *(unsigned*)&h1;
        ((uint2*)orow)[lane] = u;
    }

    if (ALPHA) {
        float sa = 0.f, sd = 0.f;
#pragma unroll
        for (int c = 0; c < CPL; c++) {
            int ch = CPL * lane + c;
            sa += v[c] * s_was[ch];
            sd += v[c] * s_wad[ch];
        }
#pragma unroll
        for (int o = 16; o; o >>= 1) {
            sa += __shfl_xor_sync(0xffffffffu, sa, o);
            sd += __shfl_xor_sync(0xffffffffu, sd, o);
        }
        if (lane == 0) { as_out[warp] = sa; ad_out[warp] = sd; }
    }
}

// ---------------- final linear + sigmoid ------------------------------------------
__global__ void final_kernel(const float* __restrict__ lw, const float* __restrict__ lb,
                             float* __restrict__ out) {
    int g = blockIdx.x * blockDim.x + threadIdx.x;
    if (g >= GG) return;
    float cnt = fmaxf(d_gcnt[g], 1.f);
    float acc = lb[0];
#pragma unroll
    for (int c = 0; c < 32; c++) acc += (d_gsum[g * 32 + c] / cnt) * lw[c];
    out[g] = 1.f / (1.f + __expf(-acc));
}

// ---------------- launch ----------------------------------------------------------
extern "C" void kernel_launch(void* const* d_in, const int* in_sizes, int n_in,
                              void* d_out, int out_size) {
    const float* x     = (const float*)d_in[0];
    const int*   ei    = (const int*)d_in[1];
    const int*   batch = (const int*)d_in[2];
    const float* w1 = (const float*)d_in[3]; const float* b1 = (const float*)d_in[4];
    const float* w2 = (const float*)d_in[5]; const float* b2 = (const float*)d_in[6];
    const float* w3 = (const float*)d_in[7]; const float* b3 = (const float*)d_in[8];
    float* out = (float*)d_out;

    int n = in_sizes[0];
    int E = in_sizes[1] / 2;
    const int* src = ei;
    const int* dst = ei + E;

    float *as0, *ad0, *as1, *ad1, *wasAll, *wadAll;
    __half *bufA, *bufBh, *wh;
    cudaGetSymbolAddress((void**)&bufA, d_bufA);
    cudaGetSymbolAddress((void**)&bufBh, d_bufBh);
    cudaGetSymbolAddress((void**)&wh, d_wh);
    cudaGetSymbolAddress((void**)&as0, d_as0);
    cudaGetSymbolAddress((void**)&ad0, d_ad0);
    cudaGetSymbolAddress((void**)&as1, d_as1);
    cudaGetSymbolAddress((void**)&ad1, d_ad1);
    cudaGetSymbolAddress((void**)&wasAll, d_was_all);
    cudaGetSymbolAddress((void**)&wadAll, d_wad_all);

    const int TPB = 256;
    int warpBlocks = (n * 32 + TPB - 1) / TPB;

    struct Layer { const float *W, *as_, *ad_, *b; int I, O; };
    Layer L[5] = {
        { (const float*)d_in[9],  (const float*)d_in[10], (const float*)d_in[11], (const float*)d_in[12],  64, 128 },
        { (const float*)d_in[13], (const float*)d_in[14], (const float*)d_in[15], (const float*)d_in[16], 128, 256 },
        { (const float*)d_in[17], (const float*)d_in[18], (const float*)d_in[19], (const float*)d_in[20], 256, 128 },
        { (const float*)d_in[21], (const float*)d_in[22], (const float*)d_in[23], (const float*)d_in[24], 128,  64 },
        { (const float*)d_in[25], (const float*)d_in[26], (const float*)d_in[27], (const float*)d_in[28],  64,  32 },
    };

    PrepArgs pa;
    for (int l = 0; l < 5; l++) {
        pa.W[l] = L[l].W; pa.as_[l] = L[l].as_; pa.ad_[l] = L[l].ad_;
        pa.I[l] = L[l].I; pa.O[l] = L[l].O;
    }
    prep_all_kernel<<<dim3(256, 5), 128>>>(pa);
    wconv_kernel<<<dim3(32, 5), 256>>>(pa);
    mlp_kernel<<<warpBlocks, TPB>>>(x, w1, b1, w2, b2, w3, b3, bufA,
                                    wasAll, wadAll, as0, ad0, n);   // also inits d_cur

    // CSR build
    count_deg_kernel<<<(E + TPB - 1) / TPB, TPB>>>(dst, E);
    int nb = (n + 1023) / 1024;
    scan_block_kernel<<<nb, 1024>>>(n);
    scan_add_fill_kernel<<<(n + 1024) / 1024, 1024>>>(n, nb);
    scatter_edges_kernel<<<(E + TPB - 1) / TPB, TPB>>>(src, dst, E);

    // ---- L1 (agg-first, I=64): agg in input space, fused GEMM ----
    gat_agg_pre_kernel<2><<<warpBlocks, TPB>>>(bufA, bufBh, as0, ad0, as1, ad1, n, 64);
    {
        dim3 grid(2, (n + 127) / 128);
        gemm_h_kernel<1><<<grid, 512>>>(bufBh, wh + 0 * WOFF, bufA, L[0].b,
                                        wasAll + 1 * 256, wadAll + 1 * 256,
                                        as1, ad1, n, 64, 128);
    }
    // ---- L2 (agg-first, I=128) ----
    gat_agg_pre_kernel<4><<<warpBlocks, TPB>>>(bufA, bufBh, as1, ad1, as0, ad0, n, 128);
    {
        dim3 grid(4, (n + 127) / 128);
        gemm_h_kernel<1><<<grid, 512>>>(bufBh, wh + 1 * WOFF, bufA, L[1].b,
                                        wasAll + 2 * 256, wadAll + 2 * 256,
                                        as0, ad0, n, 128, 256);
    }
    // ---- L3 (agg-after, O=128) ----
    {
        dim3 grid(2, (n + 127) / 128);
        gemm_h_kernel<0><<<grid, 512>>>(bufA, wh + 2 * WOFF, bufBh,
                                        nullptr, nullptr, nullptr, nullptr, nullptr,
                                        n, 256, 128);
    }
    gat_agg_kernel<4, false, false, true><<<warpBlocks, TPB>>>(
        bufBh, L[2].b, bufA, as0, ad0, as1, ad1,
        wasAll + 3 * 256, wadAll + 3 * 256, batch, n, 128);
    // ---- L4 (agg-after, O=64) ----
    {
        dim3 grid(1, (n + 127) / 128);
        gemm_h_kernel<0><<<grid, 512>>>(bufA, wh + 3 * WOFF, bufBh,
                                        nullptr, nullptr, nullptr, nullptr, nullptr,
                                        n, 128, 64);
    }
    gat_agg_kernel<2, true, false, true><<<warpBlocks, TPB>>>(
        bufBh, L[3].b, bufA, as1, ad1, as0, ad0,
        wasAll + 4 * 256, wadAll + 4 * 256, batch, n, 64);
    // ---- L5 (agg-after, O=32, fused pool) ----
    {
        dim3 grid(1, (n + 127) / 128);
        gemm_h_kernel<0><<<grid, 512>>>(bufA, wh + 4 * WOFF, bufBh,
                                        nullptr, nullptr, nullptr, nullptr, nullptr,
                                        n, 64, 32);
    }
    gat_agg_kernel<1, false, true, false><<<warpBlocks, TPB>>>(
        bufBh, L[4].b, bufA, as0, ad0, as1, ad1,
        wasAll, wadAll, batch, n, 32);

    final_kernel<<<(GG + TPB - 1) / TPB, TPB>>>((const float*)d_in[29],
                                                (const float*)d_in[30], out);
}